// round 8
// baseline (speedup 1.0000x reference)
#include <cuda_runtime.h>
#include <cstdint>

// ---------------------------------------------------------------------------
// LinearFlow: out[t,n,i] = sum_j expm(t_k * A)[i,j] * x[n,j]
//   A = 0.5*((M+M0) - (M+M0)^T), 8x8 skew-symmetric, ||tA|| <~ 0.15
//
// Phase 1: Taylor expm, output packed across i-PAIRS:
//          g_Epk[t][j][p] = f32x2( E[t][2p][j], E[t][2p+1][j] )
// Phase 2: 256 MB DRAM-bound write.
//   - f32x2 packs adjacent output components -> accumulators ARE the output
//     (no unpacking), 1 LDS.128 per j per lane (broadcast), coalesced STG.128
//   - 2 rows per lane amortize E loads; 1 full wave (512 blocks, 4 CTA/SM)
// ---------------------------------------------------------------------------

#define MS        8
#define T_MAX     512
#define TB_T      64     // t-values per apply block
#define ROWS_B    256    // n-rows per apply block (8 warps x 32 rows)
#define THREADS   256
#define KTERMS    10     // Taylor order; error ~1e-17 << fp32 eps

// Packed E: [T][j=8][p=4] u64, p = i>>1. 128 KB.
__device__ unsigned long long g_Epk[T_MAX * 32];

// ---- f32x2 helpers ---------------------------------------------------------
__device__ __forceinline__ unsigned long long pack2(float lo, float hi) {
    unsigned long long r;
    asm("mov.b64 %0, {%1, %2};" : "=l"(r) : "f"(lo), "f"(hi));
    return r;
}
__device__ __forceinline__ unsigned long long fma2(unsigned long long a,
                                                   unsigned long long b,
                                                   unsigned long long c) {
    unsigned long long d;
    asm("fma.rn.f32x2 %0, %1, %2, %3;" : "=l"(d) : "l"(a), "l"(b), "l"(c));
    return d;
}

// ---------------------------------------------------------------------------
// Phase 1: E[t] = expm(t*A), 64 threads per t, 8 t per block.
// P_1 = tA; P_k = P_{k-1} @ tA / k; E = I + sum P_k.
// ---------------------------------------------------------------------------
__global__ void expm_kernel(const float* __restrict__ t,
                            const float* __restrict__ M,
                            const float* __restrict__ M0,
                            int T) {
    __shared__ float sA[8][64];
    __shared__ float sP[2][8][64];

    const int tid = threadIdx.x;
    const int tt  = tid >> 6;
    const int e   = tid & 63;
    const int i   = e >> 3;
    const int j   = e & 7;
    const int tg  = blockIdx.x * 8 + tt;

    const float tv  = (tg < T) ? t[tg] : 0.0f;
    const float bij = M[i * 8 + j] + M0[i * 8 + j];
    const float bji = M[j * 8 + i] + M0[j * 8 + i];
    const float a   = 0.5f * (bij - bji) * tv;

    sA[tt][e]    = a;
    sP[0][tt][e] = a;
    float acc = ((i == j) ? 1.0f : 0.0f) + a;
    __syncthreads();

    int buf = 0;
    #pragma unroll
    for (int k = 2; k <= KTERMS; k++) {
        float c = 0.0f;
        #pragma unroll
        for (int m = 0; m < 8; m++)
            c = fmaf(sP[buf][tt][i * 8 + m], sA[tt][m * 8 + j], c);
        c *= (1.0f / (float)k);
        acc += c;
        sP[1 - buf][tt][e] = c;
        buf ^= 1;
        __syncthreads();
    }

    if (tg < T) {
        // i-pair packed layout: u64 index = t*32 + j*4 + (i>>1), lane = i&1
        float* dst = reinterpret_cast<float*>(g_Epk);
        dst[(tg * 32 + j * 4 + (i >> 1)) * 2 + (i & 1)] = acc;
    }
}

// ---------------------------------------------------------------------------
// Phase 2. Warp covers 32 rows. Lane L: h = L&1, rowA = rb + (L>>1),
// rowB = rowA + 16; computes components i in [4h, 4h+4) as two f32x2
// accumulators (i-pairs 2h, 2h+1). Store float4 index = t*2N + row*2 + h
// -> per warp-store 512 B contiguous.
// ---------------------------------------------------------------------------
__global__ void __launch_bounds__(THREADS)
apply_kernel(const float* __restrict__ x,
             float* __restrict__ out,
             int N) {
    __shared__ unsigned long long sE[TB_T * 32];   // 16 KB

    const int tid   = threadIdx.x;
    const int tbase = blockIdx.y * TB_T;

    // Stage packed E slab (coalesced float4 copy: 1024 f4 / 256 thr = 4 iters)
    {
        const float4* src = reinterpret_cast<const float4*>(g_Epk + (size_t)tbase * 32);
        float4* dst = reinterpret_cast<float4*>(sE);
        #pragma unroll
        for (int k = 0; k < (TB_T * 32 * 8 / 16) / THREADS; k++)
            dst[tid + k * THREADS] = src[tid + k * THREADS];
    }

    const int warp = tid >> 5;
    const int lane = tid & 31;
    const int h    = lane & 1;
    const int rb   = blockIdx.x * ROWS_B + warp * 32;
    const int rowA = rb + (lane >> 1);
    const int rowB = rowA + 16;

    // Load x rows, duplicate-packed so one reg feeds both i-lanes of fma2.
    unsigned long long xA[8], xB[8];
    {
        const float4* xpA = reinterpret_cast<const float4*>(x) + (size_t)rowA * 2;
        const float4* xpB = reinterpret_cast<const float4*>(x) + (size_t)rowB * 2;
        float4 a0 = xpA[0], a1 = xpA[1], b0 = xpB[0], b1 = xpB[1];
        xA[0] = pack2(a0.x, a0.x);  xA[1] = pack2(a0.y, a0.y);
        xA[2] = pack2(a0.z, a0.z);  xA[3] = pack2(a0.w, a0.w);
        xA[4] = pack2(a1.x, a1.x);  xA[5] = pack2(a1.y, a1.y);
        xA[6] = pack2(a1.z, a1.z);  xA[7] = pack2(a1.w, a1.w);
        xB[0] = pack2(b0.x, b0.x);  xB[1] = pack2(b0.y, b0.y);
        xB[2] = pack2(b0.z, b0.z);  xB[3] = pack2(b0.w, b0.w);
        xB[4] = pack2(b1.x, b1.x);  xB[5] = pack2(b1.y, b1.y);
        xB[6] = pack2(b1.z, b1.z);  xB[7] = pack2(b1.w, b1.w);
    }

    __syncthreads();

    ulonglong2* outv = reinterpret_cast<ulonglong2*>(out);
    const size_t fA     = (size_t)rowA * 2 + h;          // f4 index within t-plane
    const size_t f4step = (size_t)2 * N;                 // f4 per t-plane
    size_t base = (size_t)tbase * f4step;

    const unsigned long long* eB = sE + 2 * h;           // p-offset = 2h

    #pragma unroll 2
    for (int tl = 0; tl < TB_T; tl++) {
        const unsigned long long* e = eB + tl * 32;
        unsigned long long oA01 = 0ull, oA23 = 0ull, oB01 = 0ull, oB23 = 0ull;

        #pragma unroll
        for (int j = 0; j < 8; j++) {
            // one LDS.128 per j: E pairs (i=4h,4h+1) and (i=4h+2,4h+3)
            ulonglong2 ep = *reinterpret_cast<const ulonglong2*>(e + j * 4);
            oA01 = fma2(ep.x, xA[j], oA01);
            oA23 = fma2(ep.y, xA[j], oA23);
            oB01 = fma2(ep.x, xB[j], oB01);
            oB23 = fma2(ep.y, xB[j], oB23);
        }

        ulonglong2 vA; vA.x = oA01; vA.y = oA23;         // = float4 out[4h..4h+3]
        ulonglong2 vB; vB.x = oB01; vB.y = oB23;
        outv[base + fA]      = vA;
        outv[base + fA + 32] = vB;                        // rowB = rowA+16 -> +32 f4
        base += f4step;
    }
}

// ---------------------------------------------------------------------------
extern "C" void kernel_launch(void* const* d_in, const int* in_sizes, int n_in,
                              void* d_out, int out_size) {
    const float* x  = (const float*)d_in[0];   // [N, 8]
    const float* t  = (const float*)d_in[1];   // [T]
    const float* M  = (const float*)d_in[2];   // [8, 8]
    const float* M0 = (const float*)d_in[3];   // [8, 8]
    float* out = (float*)d_out;                // [T, N, 8]

    const int N = in_sizes[0] / MS;            // 16384
    const int T = in_sizes[1];                 // 512

    expm_kernel<<<(T + 7) / 8, 512>>>(t, M, M0, T);

    dim3 grid(N / ROWS_B, T / TB_T);           // (64, 8) = 512 blocks, 1 wave
    apply_kernel<<<grid, THREADS>>>(x, out, N);
}

// round 9
// speedup vs baseline: 1.1781x; 1.1781x over previous
#include <cuda_runtime.h>
#include <cstdint>

// ---------------------------------------------------------------------------
// LinearFlow: out[t,n,i] = sum_j expm(t_k * A)[i,j] * x[n,j]
//   A = 0.5*((M+M0) - (M+M0)^T), 8x8 skew-symmetric, ||tA|| <~ 0.15
//
// Phase 1: Taylor expm, output packed across i-PAIRS:
//          g_Epk[t][j][p] = f32x2( E[t][2p][j], E[t][2p+1][j] )
// Phase 2: 256 MB DRAM-bound write.
//   R7 lesson: i-pair f32x2 packing -> 1 LDS.128/j, no unpack, L1 57% (good)
//   R7 mistake: 512 blocks -> grid-limited occupancy 35% (bad)
//   R8: TB_T=32 -> 1024 blocks (R6's proven grid) + streaming stores.
// ---------------------------------------------------------------------------

#define MS        8
#define T_MAX     512
#define TB_T      32     // t-values per apply block
#define ROWS_B    256    // n-rows per apply block (8 warps x 32 rows)
#define THREADS   256
#define KTERMS    10     // Taylor order; error ~1e-17 << fp32 eps

// Packed E: [T][j=8][p=4] u64, p = i>>1. 128 KB.
__device__ unsigned long long g_Epk[T_MAX * 32];

// ---- f32x2 helpers ---------------------------------------------------------
__device__ __forceinline__ unsigned long long pack2(float lo, float hi) {
    unsigned long long r;
    asm("mov.b64 %0, {%1, %2};" : "=l"(r) : "f"(lo), "f"(hi));
    return r;
}
__device__ __forceinline__ unsigned long long fma2(unsigned long long a,
                                                   unsigned long long b,
                                                   unsigned long long c) {
    unsigned long long d;
    asm("fma.rn.f32x2 %0, %1, %2, %3;" : "=l"(d) : "l"(a), "l"(b), "l"(c));
    return d;
}
__device__ __forceinline__ void stcs_v2u64(void* p, unsigned long long a,
                                           unsigned long long b) {
    asm volatile("st.global.cs.v2.u64 [%0], {%1, %2};"
                 :: "l"(p), "l"(a), "l"(b) : "memory");
}

// ---------------------------------------------------------------------------
// Phase 1: E[t] = expm(t*A), 64 threads per t, 8 t per block.
// P_1 = tA; P_k = P_{k-1} @ tA / k; E = I + sum P_k.
// ---------------------------------------------------------------------------
__global__ void expm_kernel(const float* __restrict__ t,
                            const float* __restrict__ M,
                            const float* __restrict__ M0,
                            int T) {
    __shared__ float sA[8][64];
    __shared__ float sP[2][8][64];

    const int tid = threadIdx.x;
    const int tt  = tid >> 6;
    const int e   = tid & 63;
    const int i   = e >> 3;
    const int j   = e & 7;
    const int tg  = blockIdx.x * 8 + tt;

    const float tv  = (tg < T) ? t[tg] : 0.0f;
    const float bij = M[i * 8 + j] + M0[i * 8 + j];
    const float bji = M[j * 8 + i] + M0[j * 8 + i];
    const float a   = 0.5f * (bij - bji) * tv;

    sA[tt][e]    = a;
    sP[0][tt][e] = a;
    float acc = ((i == j) ? 1.0f : 0.0f) + a;
    __syncthreads();

    int buf = 0;
    #pragma unroll
    for (int k = 2; k <= KTERMS; k++) {
        float c = 0.0f;
        #pragma unroll
        for (int m = 0; m < 8; m++)
            c = fmaf(sP[buf][tt][i * 8 + m], sA[tt][m * 8 + j], c);
        c *= (1.0f / (float)k);
        acc += c;
        sP[1 - buf][tt][e] = c;
        buf ^= 1;
        __syncthreads();
    }

    if (tg < T) {
        // i-pair packed layout: u64 index = t*32 + j*4 + (i>>1), lane = i&1
        float* dst = reinterpret_cast<float*>(g_Epk);
        dst[(tg * 32 + j * 4 + (i >> 1)) * 2 + (i & 1)] = acc;
    }
}

// ---------------------------------------------------------------------------
// Phase 2. Warp covers 32 rows. Lane L: h = L&1, rowA = rb + (L>>1),
// rowB = rowA + 16; computes components i in [4h, 4h+4) as two f32x2
// accumulators (i-pairs 2h, 2h+1). Store float4 index = t*2N + row*2 + h
// -> two 512 B contiguous warp stores per t (streaming, evict-first).
// ---------------------------------------------------------------------------
__global__ void __launch_bounds__(THREADS)
apply_kernel(const float* __restrict__ x,
             float* __restrict__ out,
             int N) {
    __shared__ unsigned long long sE[TB_T * 32];   // 8 KB

    const int tid   = threadIdx.x;
    const int tbase = blockIdx.y * TB_T;

    // Stage packed E slab (coalesced float4 copy: 512 f4 / 256 thr = 2 iters)
    {
        const float4* src = reinterpret_cast<const float4*>(g_Epk + (size_t)tbase * 32);
        float4* dst = reinterpret_cast<float4*>(sE);
        #pragma unroll
        for (int k = 0; k < (TB_T * 32 * 8 / 16) / THREADS; k++)
            dst[tid + k * THREADS] = src[tid + k * THREADS];
    }

    const int warp = tid >> 5;
    const int lane = tid & 31;
    const int h    = lane & 1;
    const int rb   = blockIdx.x * ROWS_B + warp * 32;
    const int rowA = rb + (lane >> 1);
    const int rowB = rowA + 16;

    // Load x rows, duplicate-packed so one reg feeds both i-lanes of fma2.
    unsigned long long xA[8], xB[8];
    {
        const float4* xpA = reinterpret_cast<const float4*>(x) + (size_t)rowA * 2;
        const float4* xpB = reinterpret_cast<const float4*>(x) + (size_t)rowB * 2;
        float4 a0 = xpA[0], a1 = xpA[1], b0 = xpB[0], b1 = xpB[1];
        xA[0] = pack2(a0.x, a0.x);  xA[1] = pack2(a0.y, a0.y);
        xA[2] = pack2(a0.z, a0.z);  xA[3] = pack2(a0.w, a0.w);
        xA[4] = pack2(a1.x, a1.x);  xA[5] = pack2(a1.y, a1.y);
        xA[6] = pack2(a1.z, a1.z);  xA[7] = pack2(a1.w, a1.w);
        xB[0] = pack2(b0.x, b0.x);  xB[1] = pack2(b0.y, b0.y);
        xB[2] = pack2(b0.z, b0.z);  xB[3] = pack2(b0.w, b0.w);
        xB[4] = pack2(b1.x, b1.x);  xB[5] = pack2(b1.y, b1.y);
        xB[6] = pack2(b1.z, b1.z);  xB[7] = pack2(b1.w, b1.w);
    }

    __syncthreads();

    const size_t fA     = (size_t)rowA * 2 + h;          // f4 index within t-plane
    const size_t f4step = (size_t)2 * N;                 // f4 per t-plane
    size_t base = (size_t)tbase * f4step;
    ulonglong2* outv = reinterpret_cast<ulonglong2*>(out);

    const unsigned long long* eB = sE + 2 * h;           // p-offset = 2h

    #pragma unroll 4
    for (int tl = 0; tl < TB_T; tl++) {
        const unsigned long long* e = eB + tl * 32;
        unsigned long long oA01 = 0ull, oA23 = 0ull, oB01 = 0ull, oB23 = 0ull;

        #pragma unroll
        for (int j = 0; j < 8; j++) {
            // one LDS.128 per j: E pairs (i=4h,4h+1) and (i=4h+2,4h+3)
            ulonglong2 ep = *reinterpret_cast<const ulonglong2*>(e + j * 4);
            oA01 = fma2(ep.x, xA[j], oA01);
            oA23 = fma2(ep.y, xA[j], oA23);
            oB01 = fma2(ep.x, xB[j], oB01);
            oB23 = fma2(ep.y, xB[j], oB23);
        }

        // accumulators are already the float4 outputs [4h..4h+3]
        stcs_v2u64(outv + base + fA,      oA01, oA23);
        stcs_v2u64(outv + base + fA + 32, oB01, oB23);   // rowB = rowA+16 -> +32 f4
        base += f4step;
    }
}

// ---------------------------------------------------------------------------
extern "C" void kernel_launch(void* const* d_in, const int* in_sizes, int n_in,
                              void* d_out, int out_size) {
    const float* x  = (const float*)d_in[0];   // [N, 8]
    const float* t  = (const float*)d_in[1];   // [T]
    const float* M  = (const float*)d_in[2];   // [8, 8]
    const float* M0 = (const float*)d_in[3];   // [8, 8]
    float* out = (float*)d_out;                // [T, N, 8]

    const int N = in_sizes[0] / MS;            // 16384
    const int T = in_sizes[1];                 // 512

    expm_kernel<<<(T + 7) / 8, 512>>>(t, M, M0, T);

    dim3 grid(N / ROWS_B, T / TB_T);           // (64, 16) = 1024 blocks
    apply_kernel<<<grid, THREADS>>>(x, out, N);
}

// round 10
// speedup vs baseline: 1.1847x; 1.0056x over previous
#include <cuda_runtime.h>
#include <cstdint>

// ---------------------------------------------------------------------------
// LinearFlow: out[t,n,i] = sum_j expm(t_k * A)[i,j] * x[n,j]
//   A = 0.5*((M+M0) - (M+M0)^T), 8x8 skew-symmetric, ||tA|| <~ 0.15
//
// Phase 1: Taylor expm, output packed across i-PAIRS:
//          g_Epk[t][j][p] = f32x2( E[t][2p][j], E[t][2p+1][j] )
// Phase 2: 256 MB DRAM-bound write.
//   R7 lesson: i-pair f32x2 packing -> 1 LDS.128/j, no unpack, L1 57% (good)
//   R7 mistake: 512 blocks -> grid-limited occupancy 35% (bad)
//   R8: TB_T=32 -> 1024 blocks (R6's proven grid) + streaming stores.
// ---------------------------------------------------------------------------

#define MS        8
#define T_MAX     512
#define TB_T      32     // t-values per apply block
#define ROWS_B    256    // n-rows per apply block (8 warps x 32 rows)
#define THREADS   256
#define KTERMS    10     // Taylor order; error ~1e-17 << fp32 eps

// Packed E: [T][j=8][p=4] u64, p = i>>1. 128 KB.
__device__ unsigned long long g_Epk[T_MAX * 32];

// ---- f32x2 helpers ---------------------------------------------------------
__device__ __forceinline__ unsigned long long pack2(float lo, float hi) {
    unsigned long long r;
    asm("mov.b64 %0, {%1, %2};" : "=l"(r) : "f"(lo), "f"(hi));
    return r;
}
__device__ __forceinline__ unsigned long long fma2(unsigned long long a,
                                                   unsigned long long b,
                                                   unsigned long long c) {
    unsigned long long d;
    asm("fma.rn.f32x2 %0, %1, %2, %3;" : "=l"(d) : "l"(a), "l"(b), "l"(c));
    return d;
}
__device__ __forceinline__ void stcs_v2u64(void* p, unsigned long long a,
                                           unsigned long long b) {
    asm volatile("st.global.cs.v2.u64 [%0], {%1, %2};"
                 :: "l"(p), "l"(a), "l"(b) : "memory");
}

// ---------------------------------------------------------------------------
// Phase 1: E[t] = expm(t*A), 64 threads per t, 8 t per block.
// P_1 = tA; P_k = P_{k-1} @ tA / k; E = I + sum P_k.
// ---------------------------------------------------------------------------
__global__ void expm_kernel(const float* __restrict__ t,
                            const float* __restrict__ M,
                            const float* __restrict__ M0,
                            int T) {
    __shared__ float sA[8][64];
    __shared__ float sP[2][8][64];

    const int tid = threadIdx.x;
    const int tt  = tid >> 6;
    const int e   = tid & 63;
    const int i   = e >> 3;
    const int j   = e & 7;
    const int tg  = blockIdx.x * 8 + tt;

    const float tv  = (tg < T) ? t[tg] : 0.0f;
    const float bij = M[i * 8 + j] + M0[i * 8 + j];
    const float bji = M[j * 8 + i] + M0[j * 8 + i];
    const float a   = 0.5f * (bij - bji) * tv;

    sA[tt][e]    = a;
    sP[0][tt][e] = a;
    float acc = ((i == j) ? 1.0f : 0.0f) + a;
    __syncthreads();

    int buf = 0;
    #pragma unroll
    for (int k = 2; k <= KTERMS; k++) {
        float c = 0.0f;
        #pragma unroll
        for (int m = 0; m < 8; m++)
            c = fmaf(sP[buf][tt][i * 8 + m], sA[tt][m * 8 + j], c);
        c *= (1.0f / (float)k);
        acc += c;
        sP[1 - buf][tt][e] = c;
        buf ^= 1;
        __syncthreads();
    }

    if (tg < T) {
        // i-pair packed layout: u64 index = t*32 + j*4 + (i>>1), lane = i&1
        float* dst = reinterpret_cast<float*>(g_Epk);
        dst[(tg * 32 + j * 4 + (i >> 1)) * 2 + (i & 1)] = acc;
    }
}

// ---------------------------------------------------------------------------
// Phase 2. Warp covers 32 rows. Lane L: h = L&1, rowA = rb + (L>>1),
// rowB = rowA + 16; computes components i in [4h, 4h+4) as two f32x2
// accumulators (i-pairs 2h, 2h+1). Store float4 index = t*2N + row*2 + h
// -> two 512 B contiguous warp stores per t (streaming, evict-first).
// ---------------------------------------------------------------------------
__global__ void __launch_bounds__(THREADS)
apply_kernel(const float* __restrict__ x,
             float* __restrict__ out,
             int N) {
    __shared__ unsigned long long sE[TB_T * 32];   // 8 KB

    const int tid   = threadIdx.x;
    const int tbase = blockIdx.y * TB_T;

    // Stage packed E slab (coalesced float4 copy: 512 f4 / 256 thr = 2 iters)
    {
        const float4* src = reinterpret_cast<const float4*>(g_Epk + (size_t)tbase * 32);
        float4* dst = reinterpret_cast<float4*>(sE);
        #pragma unroll
        for (int k = 0; k < (TB_T * 32 * 8 / 16) / THREADS; k++)
            dst[tid + k * THREADS] = src[tid + k * THREADS];
    }

    const int warp = tid >> 5;
    const int lane = tid & 31;
    const int h    = lane & 1;
    const int rb   = blockIdx.x * ROWS_B + warp * 32;
    const int rowA = rb + (lane >> 1);
    const int rowB = rowA + 16;

    // Load x rows, duplicate-packed so one reg feeds both i-lanes of fma2.
    unsigned long long xA[8], xB[8];
    {
        const float4* xpA = reinterpret_cast<const float4*>(x) + (size_t)rowA * 2;
        const float4* xpB = reinterpret_cast<const float4*>(x) + (size_t)rowB * 2;
        float4 a0 = xpA[0], a1 = xpA[1], b0 = xpB[0], b1 = xpB[1];
        xA[0] = pack2(a0.x, a0.x);  xA[1] = pack2(a0.y, a0.y);
        xA[2] = pack2(a0.z, a0.z);  xA[3] = pack2(a0.w, a0.w);
        xA[4] = pack2(a1.x, a1.x);  xA[5] = pack2(a1.y, a1.y);
        xA[6] = pack2(a1.z, a1.z);  xA[7] = pack2(a1.w, a1.w);
        xB[0] = pack2(b0.x, b0.x);  xB[1] = pack2(b0.y, b0.y);
        xB[2] = pack2(b0.z, b0.z);  xB[3] = pack2(b0.w, b0.w);
        xB[4] = pack2(b1.x, b1.x);  xB[5] = pack2(b1.y, b1.y);
        xB[6] = pack2(b1.z, b1.z);  xB[7] = pack2(b1.w, b1.w);
    }

    __syncthreads();

    const size_t fA     = (size_t)rowA * 2 + h;          // f4 index within t-plane
    const size_t f4step = (size_t)2 * N;                 // f4 per t-plane
    size_t base = (size_t)tbase * f4step;
    ulonglong2* outv = reinterpret_cast<ulonglong2*>(out);

    const unsigned long long* eB = sE + 2 * h;           // p-offset = 2h

    #pragma unroll 4
    for (int tl = 0; tl < TB_T; tl++) {
        const unsigned long long* e = eB + tl * 32;
        unsigned long long oA01 = 0ull, oA23 = 0ull, oB01 = 0ull, oB23 = 0ull;

        #pragma unroll
        for (int j = 0; j < 8; j++) {
            // one LDS.128 per j: E pairs (i=4h,4h+1) and (i=4h+2,4h+3)
            ulonglong2 ep = *reinterpret_cast<const ulonglong2*>(e + j * 4);
            oA01 = fma2(ep.x, xA[j], oA01);
            oA23 = fma2(ep.y, xA[j], oA23);
            oB01 = fma2(ep.x, xB[j], oB01);
            oB23 = fma2(ep.y, xB[j], oB23);
        }

        // accumulators are already the float4 outputs [4h..4h+3]
        stcs_v2u64(outv + base + fA,      oA01, oA23);
        stcs_v2u64(outv + base + fA + 32, oB01, oB23);   // rowB = rowA+16 -> +32 f4
        base += f4step;
    }
}

// ---------------------------------------------------------------------------
extern "C" void kernel_launch(void* const* d_in, const int* in_sizes, int n_in,
                              void* d_out, int out_size) {
    const float* x  = (const float*)d_in[0];   // [N, 8]
    const float* t  = (const float*)d_in[1];   // [T]
    const float* M  = (const float*)d_in[2];   // [8, 8]
    const float* M0 = (const float*)d_in[3];   // [8, 8]
    float* out = (float*)d_out;                // [T, N, 8]

    const int N = in_sizes[0] / MS;            // 16384
    const int T = in_sizes[1];                 // 512

    expm_kernel<<<(T + 7) / 8, 512>>>(t, M, M0, T);

    dim3 grid(N / ROWS_B, T / TB_T);           // (64, 16) = 1024 blocks
    apply_kernel<<<grid, THREADS>>>(x, out, N);
}

// round 11
// speedup vs baseline: 1.2404x; 1.0471x over previous
#include <cuda_runtime.h>
#include <cstdint>

// ---------------------------------------------------------------------------
// LinearFlow: out[t,n,i] = sum_j expm(t_k * A)[i,j] * x[n,j]
//   A = 0.5*((M+M0) - (M+M0)^T), 8x8 skew-symmetric, ||tA|| <~ 0.15
//
// SINGLE fused kernel.
//   Prologue (per block): Taylor expm for this block's 16 t-values.
//     Row-parallel: thread (tl, i) owns row i of P_k in REGISTERS; the
//     recurrence row_k = row_{k-1} @ A * (t/k) needs only smem A_skew.
//     No syncthreads in the Taylor loop. E written to smem packed across
//     i-PAIRS: sE[tl][j][p] = f32x2(E[2p][j], E[2p+1][j]).
//   Main loop: 256 MB DRAM-bound write.
//     - i-pair f32x2 accumulators ARE the output (no unpack)
//     - 1 LDS.128 per j (warp-broadcast), 2 rows per lane
//     - 512 B contiguous warp stores, streaming (.cs)
//   Grid 2048 CTAs (TB_T=16): 2.77 waves @ 5 CTA/SM -> 92% wave utilization
//     (R8's 1024 CTAs = 1.38 waves = 69%, the main loss).
// ---------------------------------------------------------------------------

#define MS        8
#define TB_T      16     // t-values per block
#define ROWS_B    256    // n-rows per block (8 warps x 32 rows)
#define THREADS   256
#define KTERMS    10     // Taylor order; ||tA||<=0.15 -> error ~1e-17

// ---- f32x2 helpers ---------------------------------------------------------
__device__ __forceinline__ unsigned long long pack2(float lo, float hi) {
    unsigned long long r;
    asm("mov.b64 %0, {%1, %2};" : "=l"(r) : "f"(lo), "f"(hi));
    return r;
}
__device__ __forceinline__ unsigned long long fma2(unsigned long long a,
                                                   unsigned long long b,
                                                   unsigned long long c) {
    unsigned long long d;
    asm("fma.rn.f32x2 %0, %1, %2, %3;" : "=l"(d) : "l"(a), "l"(b), "l"(c));
    return d;
}
__device__ __forceinline__ void stcs_v2u64(void* p, unsigned long long a,
                                           unsigned long long b) {
    asm volatile("st.global.cs.v2.u64 [%0], {%1, %2};"
                 :: "l"(p), "l"(a), "l"(b) : "memory");
}

// ---------------------------------------------------------------------------
__global__ void __launch_bounds__(THREADS, 5)
fused_kernel(const float* __restrict__ x,
             const float* __restrict__ t,
             const float* __restrict__ M,
             const float* __restrict__ M0,
             float* __restrict__ out,
             int N) {
    __shared__ float sAskew[64];                   // unscaled skew(A)
    __shared__ unsigned long long sE[TB_T * 32];   // 4 KB packed E

    const int tid   = threadIdx.x;
    const int tbase = blockIdx.y * TB_T;

    // ---- stage A_skew (tiny, L2-resident after first block) ----
    if (tid < 64) {
        const int i = tid >> 3, j = tid & 7;
        sAskew[tid] = 0.5f * ((M[i * 8 + j] + M0[i * 8 + j]) -
                              (M[j * 8 + i] + M0[j * 8 + i]));
    }
    __syncthreads();

    // ---- load x rows (all threads; independent of sE) ----
    const int warp = tid >> 5;
    const int lane = tid & 31;
    const int h    = lane & 1;
    const int rb   = blockIdx.x * ROWS_B + warp * 32;
    const int rowA = rb + (lane >> 1);
    const int rowB = rowA + 16;

    unsigned long long xA[8], xB[8];
    {
        const float4* xpA = reinterpret_cast<const float4*>(x) + (size_t)rowA * 2;
        const float4* xpB = reinterpret_cast<const float4*>(x) + (size_t)rowB * 2;
        float4 a0 = xpA[0], a1 = xpA[1], b0 = xpB[0], b1 = xpB[1];
        xA[0] = pack2(a0.x, a0.x);  xA[1] = pack2(a0.y, a0.y);
        xA[2] = pack2(a0.z, a0.z);  xA[3] = pack2(a0.w, a0.w);
        xA[4] = pack2(a1.x, a1.x);  xA[5] = pack2(a1.y, a1.y);
        xA[6] = pack2(a1.z, a1.z);  xA[7] = pack2(a1.w, a1.w);
        xB[0] = pack2(b0.x, b0.x);  xB[1] = pack2(b0.y, b0.y);
        xB[2] = pack2(b0.z, b0.z);  xB[3] = pack2(b0.w, b0.w);
        xB[4] = pack2(b1.x, b1.x);  xB[5] = pack2(b1.y, b1.y);
        xB[6] = pack2(b1.z, b1.z);  xB[7] = pack2(b1.w, b1.w);
    }

    // ---- Taylor expm prologue: thread (tl, i) owns row i for t-slot tl ----
    // row_1 = tv * Askew[i][:]; row_k = (row_{k-1} @ Askew) * tv/k;
    // E row = e_i + sum_k row_k.  No syncs inside the loop.
    if (tid < TB_T * 8) {
        const int tl = tid >> 3;
        const int i  = tid & 7;
        const float tv = t[tbase + tl];

        float r[8], acc[8];
        #pragma unroll
        for (int j = 0; j < 8; j++) {
            r[j]   = tv * sAskew[i * 8 + j];
            acc[j] = ((i == j) ? 1.0f : 0.0f) + r[j];
        }
        #pragma unroll
        for (int k = 2; k <= KTERMS; k++) {
            float tmp[8];
            #pragma unroll
            for (int j = 0; j < 8; j++) {
                float c = 0.0f;
                #pragma unroll
                for (int m = 0; m < 8; m++)
                    c = fmaf(r[m], sAskew[m * 8 + j], c);
                tmp[j] = c;
            }
            const float s = tv * (1.0f / (float)k);
            #pragma unroll
            for (int j = 0; j < 8; j++) {
                r[j] = tmp[j] * s;
                acc[j] += r[j];
            }
        }
        // write packed: float slot = (tl*32 + j*4 + (i>>1))*2 + (i&1)
        float* fE = reinterpret_cast<float*>(sE);
        #pragma unroll
        for (int j = 0; j < 8; j++)
            fE[(tl * 32 + j * 4 + (i >> 1)) * 2 + (i & 1)] = acc[j];
    }
    __syncthreads();

    // ---- main loop: stream out = E @ x ----
    const size_t fA     = (size_t)rowA * 2 + h;        // f4 index within t-plane
    const size_t f4step = (size_t)2 * N;               // f4 per t-plane
    size_t base = (size_t)tbase * f4step;
    ulonglong2* outv = reinterpret_cast<ulonglong2*>(out);

    const unsigned long long* eB = sE + 2 * h;         // p-offset = 2h

    #pragma unroll 4
    for (int tl = 0; tl < TB_T; tl++) {
        const unsigned long long* e = eB + tl * 32;
        unsigned long long oA01 = 0ull, oA23 = 0ull, oB01 = 0ull, oB23 = 0ull;

        #pragma unroll
        for (int j = 0; j < 8; j++) {
            // one LDS.128 per j: E i-pairs (4h,4h+1) and (4h+2,4h+3)
            ulonglong2 ep = *reinterpret_cast<const ulonglong2*>(e + j * 4);
            oA01 = fma2(ep.x, xA[j], oA01);
            oA23 = fma2(ep.y, xA[j], oA23);
            oB01 = fma2(ep.x, xB[j], oB01);
            oB23 = fma2(ep.y, xB[j], oB23);
        }

        stcs_v2u64(outv + base + fA,      oA01, oA23);
        stcs_v2u64(outv + base + fA + 32, oB01, oB23);  // rowB = rowA+16
        base += f4step;
    }
}

// ---------------------------------------------------------------------------
extern "C" void kernel_launch(void* const* d_in, const int* in_sizes, int n_in,
                              void* d_out, int out_size) {
    const float* x  = (const float*)d_in[0];   // [N, 8]
    const float* t  = (const float*)d_in[1];   // [T]
    const float* M  = (const float*)d_in[2];   // [8, 8]
    const float* M0 = (const float*)d_in[3];   // [8, 8]
    float* out = (float*)d_out;                // [T, N, 8]

    const int N = in_sizes[0] / MS;            // 16384
    const int T = in_sizes[1];                 // 512

    dim3 grid(N / ROWS_B, T / TB_T);           // (64, 32) = 2048 blocks
    fused_kernel<<<grid, THREADS>>>(x, t, M, M0, out, N);
}